// round 1
// baseline (speedup 1.0000x reference)
#include <cuda_runtime.h>
#include <math.h>

// Problem constants
#define BB 64
#define SS 4
#define LL 64
#define CC 32
#define HH 4
#define DD 8
#define CP 16
#define LN_EPS 1e-5f

// Intermediates (allocation-free rule: __device__ globals)
__device__ float g_xbuf[BB * LL * SS * CC];   // (b, l, s, c) after row attention
__device__ float g_m[BB * LL * CC];           // (b, l, c) track-mean after col attention

// ---------------------------------------------------------------------------
// Kernel 1: embed + pos + row MHA (seq len 64, dim 32, 4 heads) + residual LN
// grid = B*S = 256 blocks, 64 threads (thread = token)
// ---------------------------------------------------------------------------
__global__ __launch_bounds__(64)
void k_row_attn(const float* __restrict__ ctcf, const float* __restrict__ hac,
                const float* __restrict__ me1,  const float* __restrict__ me3,
                const float* __restrict__ ew,   const float* __restrict__ eb,
                const float* __restrict__ pos,
                const float* __restrict__ Win,  const float* __restrict__ bin,
                const float* __restrict__ Wout, const float* __restrict__ bout,
                const float* __restrict__ lng,  const float* __restrict__ lnb)
{
    __shared__ float sk[LL][CC + 1];
    __shared__ float sv[LL][CC + 1];
    __shared__ float sWin[96 * CC];
    __shared__ float sbin[96];
    __shared__ float sWout[CC * CC];
    __shared__ float sbo[CC], sg[CC], sb2[CC];

    const int blk = blockIdx.x;
    const int b = blk >> 2;
    const int s = blk & 3;
    const int i = threadIdx.x;   // token 0..63

    const float* sig = (s == 0) ? ctcf : (s == 1) ? hac : (s == 2) ? me1 : me3;
    const float sval = sig[b * LL + i];

    float x[CC];
    #pragma unroll
    for (int c = 0; c < CC; c++)
        x[c] = sval * ew[c] + eb[c] + pos[i * CC + c];

    for (int t = i; t < 96 * CC; t += LL) sWin[t] = Win[t];
    for (int t = i; t < 96; t += LL)      sbin[t] = bin[t];
    for (int t = i; t < CC * CC; t += LL) sWout[t] = Wout[t];
    if (i < CC) { sbo[i] = bout[i]; sg[i] = lng[i]; sb2[i] = lnb[i]; }
    __syncthreads();

    // q in regs; k,v to smem
    float q[CC];
    #pragma unroll
    for (int k = 0; k < CC; k++) {
        float a = sbin[k];
        #pragma unroll
        for (int c = 0; c < CC; c++) a += x[c] * sWin[k * CC + c];
        q[k] = a;
    }
    #pragma unroll
    for (int k = 0; k < CC; k++) {
        float a = sbin[32 + k];
        #pragma unroll
        for (int c = 0; c < CC; c++) a += x[c] * sWin[(32 + k) * CC + c];
        sk[i][k] = a;
    }
    #pragma unroll
    for (int k = 0; k < CC; k++) {
        float a = sbin[64 + k];
        #pragma unroll
        for (int c = 0; c < CC; c++) a += x[c] * sWin[(64 + k) * CC + c];
        sv[i][k] = a;
    }
    __syncthreads();

    const float scale = 0.3535533905932738f;  // 1/sqrt(8)
    float o[CC];

    #pragma unroll
    for (int h = 0; h < HH; h++) {
        // pass 1: max logit
        float mx = -1e30f;
        for (int j = 0; j < LL; j++) {
            float a = 0.f;
            #pragma unroll
            for (int d = 0; d < DD; d++) a += q[h * DD + d] * sk[j][h * DD + d];
            a *= scale;
            mx = fmaxf(mx, a);
        }
        // pass 2: exp-sum + weighted accumulate
        float se = 0.f;
        float acc[DD];
        #pragma unroll
        for (int d = 0; d < DD; d++) acc[d] = 0.f;
        for (int j = 0; j < LL; j++) {
            float a = 0.f;
            #pragma unroll
            for (int d = 0; d < DD; d++) a += q[h * DD + d] * sk[j][h * DD + d];
            float p = __expf(a * scale - mx);
            se += p;
            #pragma unroll
            for (int d = 0; d < DD; d++) acc[d] += p * sv[j][h * DD + d];
        }
        float inv = 1.f / se;
        #pragma unroll
        for (int d = 0; d < DD; d++) o[h * DD + d] = acc[d] * inv;
    }

    // out proj + residual + LN
    float y[CC];
    float mu = 0.f;
    #pragma unroll
    for (int c = 0; c < CC; c++) {
        float a = sbo[c];
        #pragma unroll
        for (int k = 0; k < CC; k++) a += o[k] * sWout[c * CC + k];
        y[c] = x[c] + a;
        mu += y[c];
    }
    mu *= (1.f / CC);
    float var = 0.f;
    #pragma unroll
    for (int c = 0; c < CC; c++) { float d = y[c] - mu; var += d * d; }
    var *= (1.f / CC);
    const float rs = rsqrtf(var + LN_EPS);
    #pragma unroll
    for (int c = 0; c < CC; c++)
        g_xbuf[((b * LL + i) * SS + s) * CC + c] = (y[c] - mu) * rs * sg[c] + sb2[c];
}

// ---------------------------------------------------------------------------
// Kernel 2: column MHA (seq len 4, dim 32) + residual LN + mean over S
// grid = B * 4 chunks = 256 blocks, 64 threads (thread = (l_local, s) token)
// ---------------------------------------------------------------------------
__global__ __launch_bounds__(64)
void k_col_attn(const float* __restrict__ Win,  const float* __restrict__ bin,
                const float* __restrict__ Wout, const float* __restrict__ bout,
                const float* __restrict__ lng,  const float* __restrict__ lnb)
{
    __shared__ float sk[64][CC + 1];
    __shared__ float sv[64][CC + 1];
    __shared__ float sy[64][CC + 1];
    __shared__ float sWin[96 * CC];
    __shared__ float sbin[96];
    __shared__ float sWout[CC * CC];
    __shared__ float sbo[CC], sg[CC], sb2[CC];

    const int blk = blockIdx.x;
    const int b = blk >> 2;
    const int ch = blk & 3;                    // 16 l's per block
    const int tid = threadIdx.x;
    const int lc = tid >> 2;                   // 0..15
    const int s  = tid & 3;
    const int l  = ch * 16 + lc;

    float x[CC];
    #pragma unroll
    for (int c = 0; c < CC; c++)
        x[c] = g_xbuf[((b * LL + l) * SS + s) * CC + c];

    for (int t = tid; t < 96 * CC; t += 64) sWin[t] = Win[t];
    for (int t = tid; t < 96; t += 64)      sbin[t] = bin[t];
    for (int t = tid; t < CC * CC; t += 64) sWout[t] = Wout[t];
    if (tid < CC) { sbo[tid] = bout[tid]; sg[tid] = lng[tid]; sb2[tid] = lnb[tid]; }
    __syncthreads();

    float q[CC];
    #pragma unroll
    for (int k = 0; k < CC; k++) {
        float a = sbin[k];
        #pragma unroll
        for (int c = 0; c < CC; c++) a += x[c] * sWin[k * CC + c];
        q[k] = a;
    }
    #pragma unroll
    for (int k = 0; k < CC; k++) {
        float a = sbin[32 + k];
        #pragma unroll
        for (int c = 0; c < CC; c++) a += x[c] * sWin[(32 + k) * CC + c];
        sk[tid][k] = a;
    }
    #pragma unroll
    for (int k = 0; k < CC; k++) {
        float a = sbin[64 + k];
        #pragma unroll
        for (int c = 0; c < CC; c++) a += x[c] * sWin[(64 + k) * CC + c];
        sv[tid][k] = a;
    }
    __syncthreads();

    const float scale = 0.3535533905932738f;
    const int base = tid & ~3;   // first token of this l-group
    float o[CC];
    #pragma unroll
    for (int h = 0; h < HH; h++) {
        float lg[SS];
        float mx = -1e30f;
        #pragma unroll
        for (int j = 0; j < SS; j++) {
            float a = 0.f;
            #pragma unroll
            for (int d = 0; d < DD; d++) a += q[h * DD + d] * sk[base + j][h * DD + d];
            lg[j] = a * scale;
            mx = fmaxf(mx, lg[j]);
        }
        float se = 0.f, p4[SS];
        #pragma unroll
        for (int j = 0; j < SS; j++) { p4[j] = __expf(lg[j] - mx); se += p4[j]; }
        float inv = 1.f / se;
        #pragma unroll
        for (int d = 0; d < DD; d++) {
            float a = 0.f;
            #pragma unroll
            for (int j = 0; j < SS; j++) a += p4[j] * sv[base + j][h * DD + d];
            o[h * DD + d] = a * inv;
        }
    }

    float y[CC];
    float mu = 0.f;
    #pragma unroll
    for (int c = 0; c < CC; c++) {
        float a = sbo[c];
        #pragma unroll
        for (int k = 0; k < CC; k++) a += o[k] * sWout[c * CC + k];
        y[c] = x[c] + a;
        mu += y[c];
    }
    mu *= (1.f / CC);
    float var = 0.f;
    #pragma unroll
    for (int c = 0; c < CC; c++) { float d = y[c] - mu; var += d * d; }
    var *= (1.f / CC);
    const float rs = rsqrtf(var + LN_EPS);
    #pragma unroll
    for (int c = 0; c < CC; c++)
        sy[tid][c] = (y[c] - mu) * rs * sg[c] + sb2[c];
    __syncthreads();

    // mean over S=4 tracks for each l
    if (s == 0) {
        #pragma unroll
        for (int c = 0; c < CC; c++) {
            float m = 0.25f * (sy[base][c] + sy[base + 1][c] + sy[base + 2][c] + sy[base + 3][c]);
            g_m[(b * LL + l) * CC + c] = m;
        }
    }
}

// ---------------------------------------------------------------------------
// Kernel 3: outer-product-normalize-project-LN-SiLU, never materializing pair.
// feat[b,i,j,p] = (m_i^T W_p m_j) / max(|m_i||m_j|,1e-6) + bp -> LN(CP) -> SiLU
// grid = B * 8 i-chunks = 512 blocks, 256 threads
// ---------------------------------------------------------------------------
__global__ __launch_bounds__(256)
void k_pair(const float* __restrict__ Wp, const float* __restrict__ bp,
            const float* __restrict__ png, const float* __restrict__ pnb,
            float* __restrict__ out)
{
    __shared__ float sm[LL][CC + 1];
    __shared__ float snrm[LL];
    __shared__ float su[8][CP * CC];   // u for this i-chunk: [il][p*32+c2]
    __shared__ float sbp[CP], sg[CP], sb[CP];

    const int b  = blockIdx.x >> 3;
    const int ch = blockIdx.x & 7;
    const int tid = threadIdx.x;

    for (int t = tid; t < LL * CC; t += 256) {
        int r = t >> 5, c = t & 31;
        sm[r][c] = g_m[b * (LL * CC) + t];
    }
    if (tid < CP) { sbp[tid] = bp[tid]; sg[tid] = png[tid]; sb[tid] = pnb[tid]; }
    __syncthreads();

    if (tid < LL) {
        float a = 0.f;
        #pragma unroll
        for (int c = 0; c < CC; c++) a += sm[tid][c] * sm[tid][c];
        snrm[tid] = sqrtf(a);
    }
    __syncthreads();

    // phase 1: u[il][p*32+c2] = sum_c1 m[i][c1] * Wp[p*1024 + c1*32 + c2]
    for (int t = tid; t < 8 * CP * CC; t += 256) {
        const int il = t >> 9;
        const int k  = t & 511;
        const int p  = k >> 5;
        const int c2 = k & 31;
        const int i  = ch * 8 + il;
        float a = 0.f;
        #pragma unroll
        for (int c1 = 0; c1 < CC; c1++)
            a += sm[i][c1] * Wp[p * (CC * CC) + c1 * CC + c2];
        su[il][k] = a;
    }
    __syncthreads();

    // phase 2: per (i,j): 16 dots, normalize, LN over CP, SiLU, store (b,p,i,j)
    for (int t = tid; t < 8 * LL; t += 256) {
        const int il = t >> 6;
        const int j  = t & 63;
        const int i  = ch * 8 + il;
        const float inv = 1.f / fmaxf(snrm[i] * snrm[j], 1e-6f);

        float f[CP];
        float mu = 0.f;
        #pragma unroll
        for (int p = 0; p < CP; p++) {
            float a = 0.f;
            #pragma unroll
            for (int c = 0; c < CC; c++) a += su[il][p * CC + c] * sm[j][c];
            a = a * inv + sbp[p];
            f[p] = a;
            mu += a;
        }
        mu *= (1.f / CP);
        float var = 0.f;
        #pragma unroll
        for (int p = 0; p < CP; p++) { float d = f[p] - mu; var += d * d; }
        var *= (1.f / CP);
        const float rs = rsqrtf(var + LN_EPS);
        #pragma unroll
        for (int p = 0; p < CP; p++) {
            float xn = (f[p] - mu) * rs * sg[p] + sb[p];
            float yv = xn / (1.f + __expf(-xn));             // SiLU
            out[((b * CP + p) * LL + i) * LL + j] = yv;      // coalesced over j
        }
    }
}

// ---------------------------------------------------------------------------
extern "C" void kernel_launch(void* const* d_in, const int* in_sizes, int n_in,
                              void* d_out, int out_size)
{
    const float* ctcf = (const float*)d_in[0];
    const float* hac  = (const float*)d_in[1];
    const float* me1  = (const float*)d_in[2];
    const float* me3  = (const float*)d_in[3];
    const float* ew   = (const float*)d_in[4];
    const float* eb   = (const float*)d_in[5];
    const float* pos  = (const float*)d_in[6];
    const float* riw  = (const float*)d_in[7];
    const float* rib  = (const float*)d_in[8];
    const float* row_ = (const float*)d_in[9];
    const float* rob  = (const float*)d_in[10];
    const float* rlg  = (const float*)d_in[11];
    const float* rlb  = (const float*)d_in[12];
    const float* ciw  = (const float*)d_in[13];
    const float* cib  = (const float*)d_in[14];
    const float* cow  = (const float*)d_in[15];
    const float* cob  = (const float*)d_in[16];
    const float* clg  = (const float*)d_in[17];
    const float* clb  = (const float*)d_in[18];
    const float* pw   = (const float*)d_in[19];
    const float* pb   = (const float*)d_in[20];
    const float* plg  = (const float*)d_in[21];
    const float* plb  = (const float*)d_in[22];
    float* out = (float*)d_out;

    k_row_attn<<<BB * SS, 64>>>(ctcf, hac, me1, me3, ew, eb, pos,
                                riw, rib, row_, rob, rlg, rlb);
    k_col_attn<<<BB * 4, 64>>>(ciw, cib, cow, cob, clg, clb);
    k_pair<<<BB * 8, 256>>>(pw, pb, plg, plb, out);
}

// round 2
// speedup vs baseline: 1.6992x; 1.6992x over previous
#include <cuda_runtime.h>
#include <math.h>

#define BB 64
#define SS 4
#define LL 64
#define CC 32
#define HH 4
#define DD 8
#define CPD 16
#define LN_EPS 1e-5f
#define ST 36   // padded float stride, 16B-aligned rows

__device__ float g_xbuf[BB * LL * SS * CC];   // (b, l, s, c) after row attention
__device__ float g_m[BB * LL * CC];           // (b, l, c) track-mean after col attention

__device__ __forceinline__ float dot4(float4 a, float4 b) {
    return a.x * b.x + a.y * b.y + a.z * b.z + a.w * b.w;
}

// ---------------------------------------------------------------------------
// Kernel 1: embed + pos + row MHA (L=64, C=32, H=4) + residual LN
// grid = B*S = 256 blocks, 256 threads: tid = h*64 + i  (warp-uniform head)
// ---------------------------------------------------------------------------
__global__ __launch_bounds__(256)
void k_row_attn(const float* __restrict__ ctcf, const float* __restrict__ hac,
                const float* __restrict__ me1,  const float* __restrict__ me3,
                const float* __restrict__ ew,   const float* __restrict__ eb,
                const float* __restrict__ pos,
                const float* __restrict__ Win,  const float* __restrict__ bin,
                const float* __restrict__ Wout, const float* __restrict__ bout,
                const float* __restrict__ lng,  const float* __restrict__ lnb)
{
    __shared__ float sx[LL * ST];
    __shared__ float sk[LL * ST];
    __shared__ float sv[LL * ST];
    __shared__ float sWin[96 * CC];
    __shared__ float sWout[CC * CC];
    __shared__ float sbin[96];
    __shared__ float sbo[CC], sg[CC], sb2[CC];
    __shared__ float pmu[HH][LL];
    __shared__ float pvar[HH][LL];

    const int blk = blockIdx.x;
    const int b = blk >> 2;
    const int s = blk & 3;
    const int tid = threadIdx.x;
    const int h = tid >> 6;     // 0..3 (warp-uniform)
    const int i = tid & 63;     // token

    const float* sig = (s == 0) ? ctcf : (s == 1) ? hac : (s == 2) ? me1 : me3;

    for (int t = tid; t < 96 * CC; t += 256) sWin[t] = Win[t];
    for (int t = tid; t < CC * CC; t += 256) sWout[t] = Wout[t];
    if (tid < 96) sbin[tid] = bin[tid];
    if (tid < CC) { sbo[tid] = bout[tid]; sg[tid] = lng[tid]; sb2[tid] = lnb[tid]; }
    for (int t = tid; t < LL * CC; t += 256) {
        int tk = t >> 5, c = t & 31;
        sx[tk * ST + c] = sig[b * LL + tk] * ew[c] + eb[c] + pos[t];
    }
    __syncthreads();

    // reg-cache this token's x row
    float4 xr[8];
    #pragma unroll
    for (int c4 = 0; c4 < 8; c4++) xr[c4] = *(const float4*)&sx[i * ST + c4 * 4];

    // q in regs; k,v -> smem (this head's slice)
    float q[DD];
    #pragma unroll
    for (int r = 0; r < DD; r++) {
        const float4* w = (const float4*)&sWin[(h * DD + r) * CC];
        float a = sbin[h * DD + r];
        #pragma unroll
        for (int c4 = 0; c4 < 8; c4++) a += dot4(xr[c4], w[c4]);
        q[r] = a;
    }
    #pragma unroll
    for (int r = 0; r < DD; r++) {
        const float4* w = (const float4*)&sWin[(CC + h * DD + r) * CC];
        float a = sbin[CC + h * DD + r];
        #pragma unroll
        for (int c4 = 0; c4 < 8; c4++) a += dot4(xr[c4], w[c4]);
        sk[i * ST + h * DD + r] = a;
    }
    #pragma unroll
    for (int r = 0; r < DD; r++) {
        const float4* w = (const float4*)&sWin[(2 * CC + h * DD + r) * CC];
        float a = sbin[2 * CC + h * DD + r];
        #pragma unroll
        for (int c4 = 0; c4 < 8; c4++) a += dot4(xr[c4], w[c4]);
        sv[i * ST + h * DD + r] = a;
    }
    // residual slice (kept before sx gets reused for o)
    float4 xre0 = xr[h * 2];
    float4 xre1 = xr[h * 2 + 1];
    __syncthreads();

    // attention: single-pass softmax (logits bounded, max-shift unnecessary)
    const float scale = 0.3535533905932738f;   // 1/sqrt(8)
    float se = 0.f;
    float acc[DD];
    #pragma unroll
    for (int d = 0; d < DD; d++) acc[d] = 0.f;
    #pragma unroll 4
    for (int j = 0; j < LL; j++) {
        float4 k0 = *(const float4*)&sk[j * ST + h * DD];
        float4 k1 = *(const float4*)&sk[j * ST + h * DD + 4];
        float a = q[0]*k0.x + q[1]*k0.y + q[2]*k0.z + q[3]*k0.w
                + q[4]*k1.x + q[5]*k1.y + q[6]*k1.z + q[7]*k1.w;
        float p = __expf(a * scale);
        se += p;
        float4 v0 = *(const float4*)&sv[j * ST + h * DD];
        float4 v1 = *(const float4*)&sv[j * ST + h * DD + 4];
        acc[0] += p * v0.x; acc[1] += p * v0.y; acc[2] += p * v0.z; acc[3] += p * v0.w;
        acc[4] += p * v1.x; acc[5] += p * v1.y; acc[6] += p * v1.z; acc[7] += p * v1.w;
    }
    const float invse = 1.f / se;

    // write o into sx (sx reads finished at previous sync)
    #pragma unroll
    for (int d = 0; d < DD; d++) sx[i * ST + h * DD + d] = acc[d] * invse;
    __syncthreads();

    // out proj (this head's 8 output channels) + residual
    float4 orow[8];
    #pragma unroll
    for (int c4 = 0; c4 < 8; c4++) orow[c4] = *(const float4*)&sx[i * ST + c4 * 4];

    float y[DD];
    float part = 0.f;
    const float xres[8] = {xre0.x, xre0.y, xre0.z, xre0.w, xre1.x, xre1.y, xre1.z, xre1.w};
    #pragma unroll
    for (int d = 0; d < DD; d++) {
        const int c = h * DD + d;
        const float4* w = (const float4*)&sWout[c * CC];
        float a = sbo[c];
        #pragma unroll
        for (int c4 = 0; c4 < 8; c4++) a += dot4(orow[c4], w[c4]);
        y[d] = a + xres[d];
        part += y[d];
    }
    pmu[h][i] = part;
    __syncthreads();
    const float mu = (pmu[0][i] + pmu[1][i] + pmu[2][i] + pmu[3][i]) * (1.f / CC);
    float vp = 0.f;
    #pragma unroll
    for (int d = 0; d < DD; d++) { float dd = y[d] - mu; vp += dd * dd; }
    pvar[h][i] = vp;
    __syncthreads();
    const float var = (pvar[0][i] + pvar[1][i] + pvar[2][i] + pvar[3][i]) * (1.f / CC);
    const float rs = rsqrtf(var + LN_EPS);

    float4 o0, o1;
    o0.x = (y[0]-mu)*rs*sg[h*DD+0] + sb2[h*DD+0];
    o0.y = (y[1]-mu)*rs*sg[h*DD+1] + sb2[h*DD+1];
    o0.z = (y[2]-mu)*rs*sg[h*DD+2] + sb2[h*DD+2];
    o0.w = (y[3]-mu)*rs*sg[h*DD+3] + sb2[h*DD+3];
    o1.x = (y[4]-mu)*rs*sg[h*DD+4] + sb2[h*DD+4];
    o1.y = (y[5]-mu)*rs*sg[h*DD+5] + sb2[h*DD+5];
    o1.z = (y[6]-mu)*rs*sg[h*DD+6] + sb2[h*DD+6];
    o1.w = (y[7]-mu)*rs*sg[h*DD+7] + sb2[h*DD+7];
    const int gbase = ((b * LL + i) * SS + s) * CC + h * DD;
    *(float4*)&g_xbuf[gbase]     = o0;
    *(float4*)&g_xbuf[gbase + 4] = o1;
}

// ---------------------------------------------------------------------------
// Kernel 2: column MHA (seq=S=4 tracks) + residual LN + mean over S
// grid = B*4 = 256 blocks (b, 16-l chunk), 256 threads: tid = h*64 + (lc*4+s)
// ---------------------------------------------------------------------------
__global__ __launch_bounds__(256)
void k_col_attn(const float* __restrict__ Win,  const float* __restrict__ bin,
                const float* __restrict__ Wout, const float* __restrict__ bout,
                const float* __restrict__ lng,  const float* __restrict__ lnb)
{
    __shared__ float sx[64 * ST];
    __shared__ float sk[64 * ST];
    __shared__ float sv[64 * ST];
    __shared__ float sWin[96 * CC];
    __shared__ float sWout[CC * CC];
    __shared__ float sbin[96];
    __shared__ float sbo[CC], sg[CC], sb2[CC];
    __shared__ float pmu[HH][64];
    __shared__ float pvar[HH][64];

    const int blk = blockIdx.x;
    const int b = blk >> 2;
    const int ch = blk & 3;
    const int tid = threadIdx.x;
    const int h  = tid >> 6;     // warp-uniform
    const int tk = tid & 63;     // token = lc*4+s
    const int s  = tk & 3;

    for (int t = tid; t < 96 * CC; t += 256) sWin[t] = Win[t];
    for (int t = tid; t < CC * CC; t += 256) sWout[t] = Wout[t];
    if (tid < 96) sbin[tid] = bin[tid];
    if (tid < CC) { sbo[tid] = bout[tid]; sg[tid] = lng[tid]; sb2[tid] = lnb[tid]; }
    // tokens of this block are contiguous in g_xbuf
    const int gb = (b * 256 + ch * 64) * CC;
    for (int t = tid; t < 64 * CC; t += 256)
        sx[(t >> 5) * ST + (t & 31)] = g_xbuf[gb + t];
    __syncthreads();

    float4 xr[8];
    #pragma unroll
    for (int c4 = 0; c4 < 8; c4++) xr[c4] = *(const float4*)&sx[tk * ST + c4 * 4];

    float q[DD];
    #pragma unroll
    for (int r = 0; r < DD; r++) {
        const float4* w = (const float4*)&sWin[(h * DD + r) * CC];
        float a = sbin[h * DD + r];
        #pragma unroll
        for (int c4 = 0; c4 < 8; c4++) a += dot4(xr[c4], w[c4]);
        q[r] = a;
    }
    #pragma unroll
    for (int r = 0; r < DD; r++) {
        const float4* w = (const float4*)&sWin[(CC + h * DD + r) * CC];
        float a = sbin[CC + h * DD + r];
        #pragma unroll
        for (int c4 = 0; c4 < 8; c4++) a += dot4(xr[c4], w[c4]);
        sk[tk * ST + h * DD + r] = a;
    }
    #pragma unroll
    for (int r = 0; r < DD; r++) {
        const float4* w = (const float4*)&sWin[(2 * CC + h * DD + r) * CC];
        float a = sbin[2 * CC + h * DD + r];
        #pragma unroll
        for (int c4 = 0; c4 < 8; c4++) a += dot4(xr[c4], w[c4]);
        sv[tk * ST + h * DD + r] = a;
    }
    float4 xre0 = xr[h * 2];
    float4 xre1 = xr[h * 2 + 1];
    __syncthreads();

    // attention over the 4 tracks of this l
    const float scale = 0.3535533905932738f;
    const int base = tk & ~3;
    float se = 0.f;
    float acc[DD];
    #pragma unroll
    for (int d = 0; d < DD; d++) acc[d] = 0.f;
    #pragma unroll
    for (int j = 0; j < SS; j++) {
        float4 k0 = *(const float4*)&sk[(base + j) * ST + h * DD];
        float4 k1 = *(const float4*)&sk[(base + j) * ST + h * DD + 4];
        float a = q[0]*k0.x + q[1]*k0.y + q[2]*k0.z + q[3]*k0.w
                + q[4]*k1.x + q[5]*k1.y + q[6]*k1.z + q[7]*k1.w;
        float p = __expf(a * scale);
        se += p;
        float4 v0 = *(const float4*)&sv[(base + j) * ST + h * DD];
        float4 v1 = *(const float4*)&sv[(base + j) * ST + h * DD + 4];
        acc[0] += p * v0.x; acc[1] += p * v0.y; acc[2] += p * v0.z; acc[3] += p * v0.w;
        acc[4] += p * v1.x; acc[5] += p * v1.y; acc[6] += p * v1.z; acc[7] += p * v1.w;
    }
    const float invse = 1.f / se;

    #pragma unroll
    for (int d = 0; d < DD; d++) sx[tk * ST + h * DD + d] = acc[d] * invse;
    __syncthreads();

    float4 orow[8];
    #pragma unroll
    for (int c4 = 0; c4 < 8; c4++) orow[c4] = *(const float4*)&sx[tk * ST + c4 * 4];

    float y[DD];
    float part = 0.f;
    const float xres[8] = {xre0.x, xre0.y, xre0.z, xre0.w, xre1.x, xre1.y, xre1.z, xre1.w};
    #pragma unroll
    for (int d = 0; d < DD; d++) {
        const int c = h * DD + d;
        const float4* w = (const float4*)&sWout[c * CC];
        float a = sbo[c];
        #pragma unroll
        for (int c4 = 0; c4 < 8; c4++) a += dot4(orow[c4], w[c4]);
        y[d] = a + xres[d];
        part += y[d];
    }
    pmu[h][tk] = part;
    __syncthreads();
    const float mu = (pmu[0][tk] + pmu[1][tk] + pmu[2][tk] + pmu[3][tk]) * (1.f / CC);
    float vp = 0.f;
    #pragma unroll
    for (int d = 0; d < DD; d++) { float dd = y[d] - mu; vp += dd * dd; }
    pvar[h][tk] = vp;
    __syncthreads();
    const float var = (pvar[0][tk] + pvar[1][tk] + pvar[2][tk] + pvar[3][tk]) * (1.f / CC);
    const float rs = rsqrtf(var + LN_EPS);

    // final LN'd values, then mean over s via 4-lane shuffles (s = lane&3)
    float m0[DD];
    #pragma unroll
    for (int d = 0; d < DD; d++) {
        float v = (y[d] - mu) * rs * sg[h * DD + d] + sb2[h * DD + d];
        v += __shfl_xor_sync(0xffffffffu, v, 1);
        v += __shfl_xor_sync(0xffffffffu, v, 2);
        m0[d] = v * 0.25f;
    }
    if (s == 0) {
        const int l = ch * 16 + (tk >> 2);
        float4 a = make_float4(m0[0], m0[1], m0[2], m0[3]);
        float4 bq = make_float4(m0[4], m0[5], m0[6], m0[7]);
        *(float4*)&g_m[(b * LL + l) * CC + h * DD]     = a;
        *(float4*)&g_m[(b * LL + l) * CC + h * DD + 4] = bq;
    }
}

// ---------------------------------------------------------------------------
// Kernel 3: pair = outer(m_i,m_j)/(|m_i||m_j|) -> proj -> LN -> SiLU
// feat[b,i,j,p] = (m_i^T W_p m_j)/max(|m_i||m_j|,1e-6) + bp
// grid = B*8 = 512 blocks (b, 8-i chunk), 256 threads
// ---------------------------------------------------------------------------
__global__ __launch_bounds__(256)
void k_pair(const float* __restrict__ Wp, const float* __restrict__ bp,
            const float* __restrict__ png, const float* __restrict__ pnb,
            float* __restrict__ out)
{
    __shared__ float sm[LL * ST];
    __shared__ float snrm[LL];
    __shared__ float su[8][CPD * CC];
    __shared__ float sbp[CPD], sg[CPD], sb[CPD];

    const int b  = blockIdx.x >> 3;
    const int ch = blockIdx.x & 7;
    const int tid = threadIdx.x;

    for (int t = tid; t < LL * CC; t += 256)
        sm[(t >> 5) * ST + (t & 31)] = g_m[b * (LL * CC) + t];
    if (tid < CPD) { sbp[tid] = bp[tid]; sg[tid] = png[tid]; sb[tid] = pnb[tid]; }
    __syncthreads();

    if (tid < LL) {
        float a = 0.f;
        #pragma unroll
        for (int c = 0; c < CC; c++) { float v = sm[tid * ST + c]; a += v * v; }
        snrm[tid] = sqrtf(a);
    }
    __syncthreads();

    // phase 1: u[il][p*32+c2] = sum_c1 m[i][c1]*Wp[p*1024 + c1*32 + c2]
    for (int t = tid; t < 8 * CPD * CC; t += 256) {
        const int il = t >> 9;
        const int k  = t & 511;
        const int p  = k >> 5;
        const int c2 = k & 31;
        const int i  = ch * 8 + il;
        float a = 0.f;
        #pragma unroll
        for (int c1 = 0; c1 < CC; c1++)
            a += sm[i * ST + c1] * Wp[p * (CC * CC) + c1 * CC + c2];
        su[il][k] = a;
    }
    __syncthreads();

    // phase 2
    for (int t = tid; t < 8 * LL; t += 256) {
        const int il = t >> 6;
        const int j  = t & 63;
        const int i  = ch * 8 + il;
        const float inv = 1.f / fmaxf(snrm[i] * snrm[j], 1e-6f);

        float4 mj[8];
        #pragma unroll
        for (int c4 = 0; c4 < 8; c4++) mj[c4] = *(const float4*)&sm[j * ST + c4 * 4];

        float f[CPD];
        float mu = 0.f;
        #pragma unroll
        for (int p = 0; p < CPD; p++) {
            const float4* up = (const float4*)&su[il][p * CC];
            float a = 0.f;
            #pragma unroll
            for (int c4 = 0; c4 < 8; c4++) a += dot4(up[c4], mj[c4]);
            a = a * inv + sbp[p];
            f[p] = a;
            mu += a;
        }
        mu *= (1.f / CPD);
        float var = 0.f;
        #pragma unroll
        for (int p = 0; p < CPD; p++) { float d = f[p] - mu; var += d * d; }
        var *= (1.f / CPD);
        const float rs = rsqrtf(var + LN_EPS);
        #pragma unroll
        for (int p = 0; p < CPD; p++) {
            float xn = (f[p] - mu) * rs * sg[p] + sb[p];
            float yv = xn / (1.f + __expf(-xn));
            out[((b * CPD + p) * LL + i) * LL + j] = yv;
        }
    }
}

// ---------------------------------------------------------------------------
extern "C" void kernel_launch(void* const* d_in, const int* in_sizes, int n_in,
                              void* d_out, int out_size)
{
    const float* ctcf = (const float*)d_in[0];
    const float* hac  = (const float*)d_in[1];
    const float* me1  = (const float*)d_in[2];
    const float* me3  = (const float*)d_in[3];
    const float* ew   = (const float*)d_in[4];
    const float* eb   = (const float*)d_in[5];
    const float* pos  = (const float*)d_in[6];
    const float* riw  = (const float*)d_in[7];
    const float* rib  = (const float*)d_in[8];
    const float* row_ = (const float*)d_in[9];
    const float* rob  = (const float*)d_in[10];
    const float* rlg  = (const float*)d_in[11];
    const float* rlb  = (const float*)d_in[12];
    const float* ciw  = (const float*)d_in[13];
    const float* cib  = (const float*)d_in[14];
    const float* cow  = (const float*)d_in[15];
    const float* cob  = (const float*)d_in[16];
    const float* clg  = (const float*)d_in[17];
    const float* clb  = (const float*)d_in[18];
    const float* pw   = (const float*)d_in[19];
    const float* pb   = (const float*)d_in[20];
    const float* plg  = (const float*)d_in[21];
    const float* plb  = (const float*)d_in[22];
    float* out = (float*)d_out;

    k_row_attn<<<BB * SS, 256>>>(ctcf, hac, me1, me3, ew, eb, pos,
                                 riw, rib, row_, rob, rlg, rlb);
    k_col_attn<<<BB * 4, 256>>>(ciw, cib, cow, cob, clg, clb);
    k_pair<<<BB * 8, 256>>>(pw, pb, plg, plb, out);
}